// round 10
// baseline (speedup 1.0000x reference)
#include <cuda_runtime.h>

#define FULL 0xFFFFFFFFu

// bf16-packed user table: row = 16 u32, u32 k = dims (2k lo, 2k+1 hi)
__device__ unsigned g_ut16[100000 * 16];
// Precomputed v[i,d] = sum_e W_bil[d,e] * item_table[i,e]  (f32)
__device__ float g_vtab[50000 * 32];
// Mask dtype mode: 0 = int32, 1 = float32, 2 = uint8
__device__ int g_mask_mode;

__device__ __forceinline__ unsigned packbf(float hi, float lo) {
    unsigned d; asm("cvt.rn.bf16x2.f32 %0,%1,%2;" : "=r"(d) : "f"(hi), "f"(lo)); return d;
}
__device__ __forceinline__ float blo(unsigned w) { return __int_as_float((int)(w << 16)); }
__device__ __forceinline__ float bhi(unsigned w) { return __int_as_float((int)(w & 0xFFFF0000u)); }

// ---------------------------------------------------------------------------
// Precompute 1: pack user_table rows to bf16.
// ---------------------------------------------------------------------------
__global__ void __launch_bounds__(256) convert_kernel(
    const float4* __restrict__ ut4, int n4)
{
    int t = blockIdx.x * blockDim.x + threadIdx.x;
    if (t < n4) {
        float4 f = ut4[t];
        g_ut16[2 * t]     = packbf(f.y, f.x);
        g_ut16[2 * t + 1] = packbf(f.w, f.z);
    }
}

// ---------------------------------------------------------------------------
// Precompute 2: one warp per item row: v = W_bil @ item_e (f32). Sniffs mask
// dtype from word 0 (mask[0,0] guaranteed true since lengths >= 1).
// ---------------------------------------------------------------------------
__global__ void __launch_bounds__(256) vtab_kernel(
    const float* __restrict__ W_bil,
    const float* __restrict__ item_table,
    const unsigned int* __restrict__ mask_words,
    int NI)
{
    __shared__ float WT[32 * 33];
    int t = threadIdx.x;

    if (blockIdx.x == 0 && t == 0) {
        unsigned int w0 = mask_words[0];
        int mode;
        if (w0 == 1u)               mode = 0;
        else if (w0 == 0x3F800000u) mode = 1;
        else                        mode = 2;
        g_mask_mode = mode;
    }

    for (int k = t; k < 1024; k += blockDim.x) {
        int d = k >> 5, e = k & 31;
        WT[e * 33 + d] = W_bil[k];
    }
    __syncthreads();

    int warp = t >> 5, lane = t & 31;
    int i = blockIdx.x * (blockDim.x >> 5) + warp;
    if (i >= NI) return;

    float x = item_table[i * 32 + lane];
    float v = 0.f;
    #pragma unroll
    for (int e = 0; e < 32; e++)
        v = fmaf(WT[e * 33 + lane], __shfl_sync(FULL, x, e), v);
    g_vtab[i * 32 + lane] = v;
}

// ---------------------------------------------------------------------------
// Main kernel: one warp, TWO pairs per iteration. lane = (g = lane>>3 member
// group, c = lane&7 4-dim chunk). Members gathered as bf16 uint2 (LDG.64,
// 4 lines/LDG), unpacked to f32 at use; all math f32. W1 via smem reload.
// launch_bounds(256,4) caps regs at 64 for 4 CTAs/SM.
// ---------------------------------------------------------------------------
__global__ void __launch_bounds__(256, 4) bilinear_main_kernel(
    const int*           __restrict__ item_inputs,
    const int*           __restrict__ member_ids,
    const void*          __restrict__ member_mask,
    const float*         __restrict__ item_table,
    const float*         __restrict__ b_bil,
    const float*         __restrict__ W1,
    const float*         __restrict__ b1,
    const float*         __restrict__ W2,
    const float*         __restrict__ b2,
    float*               __restrict__ out,
    int B)
{
    __shared__ float w1s[768];      // W1 [8][96]
    for (int k = threadIdx.x; k < 768; k += 256) w1s[k] = W1[k];
    __syncthreads();

    const int lane   = threadIdx.x & 31;
    const int warp   = (blockIdx.x * blockDim.x + threadIdx.x) >> 5;
    const int nwarps = (gridDim.x * blockDim.x) >> 5;

    const int g   = lane >> 3;        // member group 0..3
    const int c   = lane & 7;         // dim chunk 0..7 (dims 4c..4c+3)
    const int rho = (c >> 2) & 1;

    const int j0 = 2 * g + rho;       // owned MLP unit
    const int j1 = 2 * g + (1 ^ rho);

    const float b1c = b1[j0];
    const float w2c = W2[j0] * 0.25f;
    const float bb  = b_bil[0];
    const float b2v = b2[0];
    const int   mmode = g_mask_mode;
    const int   half  = lane >> 4;
    const int   memi  = lane & 15;

    const unsigned w1_0 = (unsigned)__cvta_generic_to_shared(&w1s[j0 * 96 + 4 * c]);
    const unsigned w1_1 = (unsigned)__cvta_generic_to_shared(&w1s[j1 * 96 + 4 * c]);

    const float4* __restrict__ it4p = (const float4*)item_table;
    const float4* __restrict__ vt4p = (const float4*)g_vtab;
    const uint2*  __restrict__ ut2  = (const uint2*)g_ut16;

    for (int base = 2 * warp; base < B; base += 2 * nwarps) {
        const int bA = base;
        const int bB = (base + 1 < B) ? base + 1 : base;

        const int itmA = item_inputs[bA];
        const int itmB = item_inputs[bB];
        const float4 itA = it4p[itmA * 8 + c];
        const float4 vA  = vt4p[itmA * 8 + c];
        const float4 itB = it4p[itmB * 8 + c];
        const float4 vB  = vt4p[itmB * 8 + c];

        const int bH  = half ? bB : bA;
        const int mid = member_ids[bH * 16 + memi];

        int mkbit;
        if (mmode == 0) {
            mkbit = (((const int*)member_mask)[bH * 16 + memi] != 0);
        } else if (mmode == 1) {
            mkbit = (((const float*)member_mask)[bH * 16 + memi] != 0.f);
        } else {
            mkbit = (((const unsigned char*)member_mask)[bH * 16 + memi] != 0);
        }
        const int pk = mid | (mkbit << 31);

        // Distribute packed id+mask: slot i = member 4i+g (uniform across c).
        const int pA0 = __shfl_sync(FULL, pk,      0 + g);
        const int pA1 = __shfl_sync(FULL, pk,      4 + g);
        const int pA2 = __shfl_sync(FULL, pk,      8 + g);
        const int pA3 = __shfl_sync(FULL, pk,     12 + g);
        const int pB0 = __shfl_sync(FULL, pk, 16 + 0 + g);
        const int pB1 = __shfl_sync(FULL, pk, 16 + 4 + g);
        const int pB2 = __shfl_sync(FULL, pk, 16 + 8 + g);
        const int pB3 = __shfl_sync(FULL, pk, 16 + 12 + g);

        // Gathers (bf16 rows = 64B): LDG.64, 4 rows per warp-LDG.
        const uint2 mA0 = ut2[(pA0 & 0x7FFFFFFF) * 8 + c];
        const uint2 mA1 = ut2[(pA1 & 0x7FFFFFFF) * 8 + c];
        const uint2 mA2 = ut2[(pA2 & 0x7FFFFFFF) * 8 + c];
        const uint2 mA3 = ut2[(pA3 & 0x7FFFFFFF) * 8 + c];
        const uint2 mB0 = ut2[(pB0 & 0x7FFFFFFF) * 8 + c];
        const uint2 mB1 = ut2[(pB1 & 0x7FFFFFFF) * 8 + c];
        const uint2 mB2 = ut2[(pB2 & 0x7FFFFFFF) * 8 + c];
        const uint2 mB3 = ut2[(pB3 & 0x7FFFFFFF) * 8 + c];

        // Compress mask sign bits; frees the pk registers early.
        const unsigned mbA = ((unsigned)pA0 >> 31)        | (((unsigned)pA1 >> 30) & 2u)
                           | (((unsigned)pA2 >> 29) & 4u) | (((unsigned)pA3 >> 28) & 8u);
        const unsigned mbB = ((unsigned)pB0 >> 31)        | (((unsigned)pB1 >> 30) & 2u)
                           | (((unsigned)pB2 >> 29) & 4u) | (((unsigned)pB3 >> 28) & 8u);

        // Score partial dots (f32, bf16 unpack at use) + replicated reduce.
        float sA0 = fmaf(blo(mA0.x), vA.x, fmaf(bhi(mA0.x), vA.y,
                    fmaf(blo(mA0.y), vA.z, bhi(mA0.y) * vA.w)));
        float sA1 = fmaf(blo(mA1.x), vA.x, fmaf(bhi(mA1.x), vA.y,
                    fmaf(blo(mA1.y), vA.z, bhi(mA1.y) * vA.w)));
        float sA2 = fmaf(blo(mA2.x), vA.x, fmaf(bhi(mA2.x), vA.y,
                    fmaf(blo(mA2.y), vA.z, bhi(mA2.y) * vA.w)));
        float sA3 = fmaf(blo(mA3.x), vA.x, fmaf(bhi(mA3.x), vA.y,
                    fmaf(blo(mA3.y), vA.z, bhi(mA3.y) * vA.w)));
        float sB0 = fmaf(blo(mB0.x), vB.x, fmaf(bhi(mB0.x), vB.y,
                    fmaf(blo(mB0.y), vB.z, bhi(mB0.y) * vB.w)));
        float sB1 = fmaf(blo(mB1.x), vB.x, fmaf(bhi(mB1.x), vB.y,
                    fmaf(blo(mB1.y), vB.z, bhi(mB1.y) * vB.w)));
        float sB2 = fmaf(blo(mB2.x), vB.x, fmaf(bhi(mB2.x), vB.y,
                    fmaf(blo(mB2.y), vB.z, bhi(mB2.y) * vB.w)));
        float sB3 = fmaf(blo(mB3.x), vB.x, fmaf(bhi(mB3.x), vB.y,
                    fmaf(blo(mB3.y), vB.z, bhi(mB3.y) * vB.w)));

        sA0 += __shfl_xor_sync(FULL, sA0, 4); sA1 += __shfl_xor_sync(FULL, sA1, 4);
        sA2 += __shfl_xor_sync(FULL, sA2, 4); sA3 += __shfl_xor_sync(FULL, sA3, 4);
        sB0 += __shfl_xor_sync(FULL, sB0, 4); sB1 += __shfl_xor_sync(FULL, sB1, 4);
        sB2 += __shfl_xor_sync(FULL, sB2, 4); sB3 += __shfl_xor_sync(FULL, sB3, 4);
        sA0 += __shfl_xor_sync(FULL, sA0, 2); sA1 += __shfl_xor_sync(FULL, sA1, 2);
        sA2 += __shfl_xor_sync(FULL, sA2, 2); sA3 += __shfl_xor_sync(FULL, sA3, 2);
        sB0 += __shfl_xor_sync(FULL, sB0, 2); sB1 += __shfl_xor_sync(FULL, sB1, 2);
        sB2 += __shfl_xor_sync(FULL, sB2, 2); sB3 += __shfl_xor_sync(FULL, sB3, 2);
        sA0 += __shfl_xor_sync(FULL, sA0, 1); sA1 += __shfl_xor_sync(FULL, sA1, 1);
        sA2 += __shfl_xor_sync(FULL, sA2, 1); sA3 += __shfl_xor_sync(FULL, sA3, 1);
        sB0 += __shfl_xor_sync(FULL, sB0, 1); sB1 += __shfl_xor_sync(FULL, sB1, 1);
        sB2 += __shfl_xor_sync(FULL, sB2, 1); sB3 += __shfl_xor_sync(FULL, sB3, 1);

        // Masked weights, locally on every lane.
        const float wA0 = (mbA & 1u) ? (sA0 + bb) : 0.f;
        const float wA1 = (mbA & 2u) ? (sA1 + bb) : 0.f;
        const float wA2 = (mbA & 4u) ? (sA2 + bb) : 0.f;
        const float wA3 = (mbA & 8u) ? (sA3 + bb) : 0.f;
        const float wB0 = (mbB & 1u) ? (sB0 + bb) : 0.f;
        const float wB1 = (mbB & 2u) ? (sB1 + bb) : 0.f;
        const float wB2 = (mbB & 4u) ? (sB2 + bb) : 0.f;
        const float wB3 = (mbB & 8u) ? (sB3 + bb) : 0.f;

        // fu partials (unpack again), then reduce over g (xor 8, 16).
        float fAx = wA0 * blo(mA0.x), fAy = wA0 * bhi(mA0.x);
        float fAz = wA0 * blo(mA0.y), fAw = wA0 * bhi(mA0.y);
        fAx = fmaf(wA1, blo(mA1.x), fAx); fAy = fmaf(wA1, bhi(mA1.x), fAy);
        fAz = fmaf(wA1, blo(mA1.y), fAz); fAw = fmaf(wA1, bhi(mA1.y), fAw);
        fAx = fmaf(wA2, blo(mA2.x), fAx); fAy = fmaf(wA2, bhi(mA2.x), fAy);
        fAz = fmaf(wA2, blo(mA2.y), fAz); fAw = fmaf(wA2, bhi(mA2.y), fAw);
        fAx = fmaf(wA3, blo(mA3.x), fAx); fAy = fmaf(wA3, bhi(mA3.x), fAy);
        fAz = fmaf(wA3, blo(mA3.y), fAz); fAw = fmaf(wA3, bhi(mA3.y), fAw);

        float fBx = wB0 * blo(mB0.x), fBy = wB0 * bhi(mB0.x);
        float fBz = wB0 * blo(mB0.y), fBw = wB0 * bhi(mB0.y);
        fBx = fmaf(wB1, blo(mB1.x), fBx); fBy = fmaf(wB1, bhi(mB1.x), fBy);
        fBz = fmaf(wB1, blo(mB1.y), fBz); fBw = fmaf(wB1, bhi(mB1.y), fBw);
        fBx = fmaf(wB2, blo(mB2.x), fBx); fBy = fmaf(wB2, bhi(mB2.x), fBy);
        fBz = fmaf(wB2, blo(mB2.y), fBz); fBw = fmaf(wB2, bhi(mB2.y), fBw);
        fBx = fmaf(wB3, blo(mB3.x), fBx); fBy = fmaf(wB3, bhi(mB3.x), fBy);
        fBz = fmaf(wB3, blo(mB3.y), fBz); fBw = fmaf(wB3, bhi(mB3.y), fBw);

        fAx += __shfl_xor_sync(FULL, fAx, 8);  fAy += __shfl_xor_sync(FULL, fAy, 8);
        fAz += __shfl_xor_sync(FULL, fAz, 8);  fAw += __shfl_xor_sync(FULL, fAw, 8);
        fBx += __shfl_xor_sync(FULL, fBx, 8);  fBy += __shfl_xor_sync(FULL, fBy, 8);
        fBz += __shfl_xor_sync(FULL, fBz, 8);  fBw += __shfl_xor_sync(FULL, fBw, 8);
        fAx += __shfl_xor_sync(FULL, fAx, 16); fAy += __shfl_xor_sync(FULL, fAy, 16);
        fAz += __shfl_xor_sync(FULL, fAz, 16); fAw += __shfl_xor_sync(FULL, fAw, 16);
        fBx += __shfl_xor_sync(FULL, fBx, 16); fBy += __shfl_xor_sync(FULL, fBy, 16);
        fBz += __shfl_xor_sync(FULL, fBz, 16); fBw += __shfl_xor_sync(FULL, fBw, 16);

        // MLP layer 1. ne = fu*it.
        const float nAx = fAx * itA.x, nAy = fAy * itA.y;
        const float nAz = fAz * itA.z, nAw = fAw * itA.w;
        const float nBx = fBx * itB.x, nBy = fBy * itB.y;
        const float nBz = fBz * itB.z, nBw = fBw * itB.w;

        // Reload W1 slices from smem (volatile: never hoisted into regs).
        float a00,a01,a02,a03, b00,b01,b02,b03, c00,c01,c02,c03;
        float a10,a11,a12,a13, b10,b11,b12,b13, c10,c11,c12,c13;
        asm volatile("ld.shared.v4.f32 {%0,%1,%2,%3},[%4];"
            : "=f"(a00),"=f"(a01),"=f"(a02),"=f"(a03) : "r"(w1_0));
        asm volatile("ld.shared.v4.f32 {%0,%1,%2,%3},[%4];"
            : "=f"(b00),"=f"(b01),"=f"(b02),"=f"(b03) : "r"(w1_0 + 128));
        asm volatile("ld.shared.v4.f32 {%0,%1,%2,%3},[%4];"
            : "=f"(c00),"=f"(c01),"=f"(c02),"=f"(c03) : "r"(w1_0 + 256));
        asm volatile("ld.shared.v4.f32 {%0,%1,%2,%3},[%4];"
            : "=f"(a10),"=f"(a11),"=f"(a12),"=f"(a13) : "r"(w1_1));
        asm volatile("ld.shared.v4.f32 {%0,%1,%2,%3},[%4];"
            : "=f"(b10),"=f"(b11),"=f"(b12),"=f"(b13) : "r"(w1_1 + 128));
        asm volatile("ld.shared.v4.f32 {%0,%1,%2,%3},[%4];"
            : "=f"(c10),"=f"(c11),"=f"(c12),"=f"(c13) : "r"(w1_1 + 256));

        float PA0, PA1, PB0, PB1;
        {
            float t;
            t = a00 * nAx; t = fmaf(b00, fAx, t); t = fmaf(c00, itA.x, t);
            t = fmaf(a01, nAy, t); t = fmaf(b01, fAy, t); t = fmaf(c01, itA.y, t);
            t = fmaf(a02, nAz, t); t = fmaf(b02, fAz, t); t = fmaf(c02, itA.z, t);
            t = fmaf(a03, nAw, t); t = fmaf(b03, fAw, t); t = fmaf(c03, itA.w, t);
            PA0 = t;
            t = a10 * nAx; t = fmaf(b10, fAx, t); t = fmaf(c10, itA.x, t);
            t = fmaf(a11, nAy, t); t = fmaf(b11, fAy, t); t = fmaf(c11, itA.y, t);
            t = fmaf(a12, nAz, t); t = fmaf(b12, fAz, t); t = fmaf(c12, itA.z, t);
            t = fmaf(a13, nAw, t); t = fmaf(b13, fAw, t); t = fmaf(c13, itA.w, t);
            PA1 = t;
            t = a00 * nBx; t = fmaf(b00, fBx, t); t = fmaf(c00, itB.x, t);
            t = fmaf(a01, nBy, t); t = fmaf(b01, fBy, t); t = fmaf(c01, itB.y, t);
            t = fmaf(a02, nBz, t); t = fmaf(b02, fBz, t); t = fmaf(c02, itB.z, t);
            t = fmaf(a03, nBw, t); t = fmaf(b03, fBw, t); t = fmaf(c03, itB.w, t);
            PB0 = t;
            t = a10 * nBx; t = fmaf(b10, fBx, t); t = fmaf(c10, itB.x, t);
            t = fmaf(a11, nBy, t); t = fmaf(b11, fBy, t); t = fmaf(c11, itB.y, t);
            t = fmaf(a12, nBz, t); t = fmaf(b12, fBz, t); t = fmaf(c12, itB.z, t);
            t = fmaf(a13, nBw, t); t = fmaf(b13, fBw, t); t = fmaf(c13, itB.w, t);
            PB1 = t;
        }

        // Select-free MLP reduce (xor 4, 2, 1): lane owns H_{j0} per pair.
        float hA = PA0 + __shfl_xor_sync(FULL, PA1, 4);
        float hB = PB0 + __shfl_xor_sync(FULL, PB1, 4);
        hA += __shfl_xor_sync(FULL, hA, 2);
        hB += __shfl_xor_sync(FULL, hB, 2);
        hA += __shfl_xor_sync(FULL, hA, 1);
        hB += __shfl_xor_sync(FULL, hB, 1);

        // Output layer, combined half-split tail reduce for both pairs.
        const float tA = w2c * fmaxf(hA + b1c, 0.f);
        const float tB = w2c * fmaxf(hB + b1c, 0.f);
        float x    = half ? tB : tA;
        float send = half ? tA : tB;
        x += __shfl_xor_sync(FULL, send, 16);
        x += __shfl_xor_sync(FULL, x, 8);
        x += __shfl_xor_sync(FULL, x, 4);
        x += __shfl_xor_sync(FULL, x, 2);
        x += __shfl_xor_sync(FULL, x, 1);
        // lanes 0-15 hold tvA, lanes 16-31 hold tvB.

        const float y  = 1.f / (1.f + __expf(-(x + b2v)));
        const float yB = __shfl_sync(FULL, y, 16);
        if (lane == 0) {
            if (bB != bA) {
                *(float2*)(out + base) = make_float2(y, yB);
            } else {
                out[base] = y;
            }
        }
    }
}

// ---------------------------------------------------------------------------
extern "C" void kernel_launch(void* const* d_in, const int* in_sizes, int n_in,
                              void* d_out, int out_size)
{
    const int*   item_inputs = (const int*)  d_in[0];
    const int*   member_ids  = (const int*)  d_in[1];
    const void*  member_mask =               d_in[2];
    const float* user_table  = (const float*)d_in[3];
    const float* item_table  = (const float*)d_in[4];
    const float* W_bil       = (const float*)d_in[5];
    const float* b_bil       = (const float*)d_in[6];
    const float* W1          = (const float*)d_in[7];
    const float* b1          = (const float*)d_in[8];
    const float* W2          = (const float*)d_in[9];
    const float* b2          = (const float*)d_in[10];
    float* out = (float*)d_out;

    const int B  = in_sizes[0];
    int NU = in_sizes[3] / 32;
    if (NU > 100000) NU = 100000;   // g_ut16 capacity
    int NI = in_sizes[4] / 32;
    if (NI > 50000) NI = 50000;     // g_vtab capacity

    const int n4 = NU * 8;
    convert_kernel<<<(n4 + 255) / 256, 256>>>((const float4*)user_table, n4);
    vtab_kernel<<<(NI + 7) / 8, 256>>>(W_bil, item_table,
                                       (const unsigned int*)member_mask, NI);
    bilinear_main_kernel<<<592, 256>>>(item_inputs, member_ids, member_mask,
                                       item_table, b_bil, W1, b1, W2, b2, out, B);
}

// round 12
// speedup vs baseline: 1.3319x; 1.3319x over previous
#include <cuda_runtime.h>

#define FULL 0xFFFFFFFFu

// bf16-packed user table: row = 16 u32, u32 k = dims (2k lo, 2k+1 hi)
__device__ unsigned g_ut16[100000 * 16];
// Precomputed v[i,d] = sum_e W_bil[d,e] * item_table[i,e]  (f32)
__device__ float g_vtab[50000 * 32];
// Mask dtype mode: 0 = int32, 1 = float32, 2 = uint8
__device__ int g_mask_mode;

__device__ __forceinline__ unsigned packbf(float hi, float lo) {
    unsigned d; asm("cvt.rn.bf16x2.f32 %0,%1,%2;" : "=r"(d) : "f"(hi), "f"(lo)); return d;
}
__device__ __forceinline__ float blo(unsigned w) { return __int_as_float((int)(w << 16)); }
__device__ __forceinline__ float bhi(unsigned w) { return __int_as_float((int)(w & 0xFFFF0000u)); }

// ---------------------------------------------------------------------------
// Precompute 1: pack user_table rows to bf16. Each thread: 8 floats -> uint4.
// ---------------------------------------------------------------------------
__global__ void __launch_bounds__(256) convert_kernel(
    const float4* __restrict__ ut4, int n16)
{
    int t = blockIdx.x * blockDim.x + threadIdx.x;
    if (t < n16) {
        float4 f0 = ut4[2 * t];
        float4 f1 = ut4[2 * t + 1];
        uint4 o;
        o.x = packbf(f0.y, f0.x);
        o.y = packbf(f0.w, f0.z);
        o.z = packbf(f1.y, f1.x);
        o.w = packbf(f1.w, f1.z);
        ((uint4*)g_ut16)[t] = o;
    }
}

// ---------------------------------------------------------------------------
// Precompute 2: one warp per item row: v = W_bil @ item_e (f32). Sniffs mask
// dtype from word 0 (mask[0,0] guaranteed true since lengths >= 1).
// ---------------------------------------------------------------------------
__global__ void __launch_bounds__(256) vtab_kernel(
    const float* __restrict__ W_bil,
    const float* __restrict__ item_table,
    const unsigned int* __restrict__ mask_words,
    int NI)
{
    __shared__ float WT[32 * 33];
    int t = threadIdx.x;

    if (blockIdx.x == 0 && t == 0) {
        unsigned int w0 = mask_words[0];
        int mode;
        if (w0 == 1u)               mode = 0;
        else if (w0 == 0x3F800000u) mode = 1;
        else                        mode = 2;
        g_mask_mode = mode;
    }

    for (int k = t; k < 1024; k += blockDim.x) {
        int d = k >> 5, e = k & 31;
        WT[e * 33 + d] = W_bil[k];
    }
    __syncthreads();

    int warp = t >> 5, lane = t & 31;
    int i = blockIdx.x * (blockDim.x >> 5) + warp;
    if (i >= NI) return;

    float x = item_table[i * 32 + lane];
    float v = 0.f;
    #pragma unroll
    for (int e = 0; e < 32; e++)
        v = fmaf(WT[e * 33 + lane], __shfl_sync(FULL, x, e), v);
    g_vtab[i * 32 + lane] = v;
}

// ---------------------------------------------------------------------------
// Main kernel: one warp, TWO pairs per iteration. lane = (g = lane>>3 member
// group, c = lane&7 4-dim chunk). Members gathered as bf16 uint2 (LDG.64,
// 4x64B lines/LDG), unpacked to f32 at use; all math f32. W1 via smem reload.
// 128-thread blocks, launch_bounds(128,6): cap 85 regs (spill-free regime);
// natural ~66-72 regs -> 7 CTAs/SM = 28 warps.
// ---------------------------------------------------------------------------
__global__ void __launch_bounds__(128, 6) bilinear_main_kernel(
    const int*           __restrict__ item_inputs,
    const int*           __restrict__ member_ids,
    const void*          __restrict__ member_mask,
    const float*         __restrict__ item_table,
    const float*         __restrict__ b_bil,
    const float*         __restrict__ W1,
    const float*         __restrict__ b1,
    const float*         __restrict__ W2,
    const float*         __restrict__ b2,
    float*               __restrict__ out,
    int B)
{
    __shared__ float w1s[768];      // W1 [8][96]
    for (int k = threadIdx.x; k < 768; k += 128) w1s[k] = W1[k];
    __syncthreads();

    const int lane   = threadIdx.x & 31;
    const int warp   = (blockIdx.x * blockDim.x + threadIdx.x) >> 5;
    const int nwarps = (gridDim.x * blockDim.x) >> 5;

    const int g   = lane >> 3;        // member group 0..3
    const int c   = lane & 7;         // dim chunk 0..7 (dims 4c..4c+3)
    const int rho = (c >> 2) & 1;

    const int j0 = 2 * g + rho;       // owned MLP unit
    const int j1 = 2 * g + (1 ^ rho);

    const float b1c = b1[j0];
    const float w2c = W2[j0] * 0.25f;
    const float bb  = b_bil[0];
    const float b2v = b2[0];
    const int   mmode = g_mask_mode;
    const int   half  = lane >> 4;
    const int   memi  = lane & 15;

    const unsigned w1_0 = (unsigned)__cvta_generic_to_shared(&w1s[j0 * 96 + 4 * c]);
    const unsigned w1_1 = (unsigned)__cvta_generic_to_shared(&w1s[j1 * 96 + 4 * c]);

    const float4* __restrict__ it4p = (const float4*)item_table;
    const float4* __restrict__ vt4p = (const float4*)g_vtab;
    const uint2*  __restrict__ ut2  = (const uint2*)g_ut16;

    for (int base = 2 * warp; base < B; base += 2 * nwarps) {
        const int bA = base;
        const int bB = (base + 1 < B) ? base + 1 : base;

        const int itmA = item_inputs[bA];
        const int itmB = item_inputs[bB];
        const float4 itA = it4p[itmA * 8 + c];
        const float4 vA  = vt4p[itmA * 8 + c];
        const float4 itB = it4p[itmB * 8 + c];
        const float4 vB  = vt4p[itmB * 8 + c];

        const int bH  = half ? bB : bA;
        const int mid = member_ids[bH * 16 + memi];

        int mkbit;
        if (mmode == 0) {
            mkbit = (((const int*)member_mask)[bH * 16 + memi] != 0);
        } else if (mmode == 1) {
            mkbit = (((const float*)member_mask)[bH * 16 + memi] != 0.f);
        } else {
            mkbit = (((const unsigned char*)member_mask)[bH * 16 + memi] != 0);
        }
        const int pk = mid | (mkbit << 31);

        // Distribute packed id+mask: slot i = member 4i+g (uniform across c).
        const int pA0 = __shfl_sync(FULL, pk,      0 + g);
        const int pA1 = __shfl_sync(FULL, pk,      4 + g);
        const int pA2 = __shfl_sync(FULL, pk,      8 + g);
        const int pA3 = __shfl_sync(FULL, pk,     12 + g);
        const int pB0 = __shfl_sync(FULL, pk, 16 + 0 + g);
        const int pB1 = __shfl_sync(FULL, pk, 16 + 4 + g);
        const int pB2 = __shfl_sync(FULL, pk, 16 + 8 + g);
        const int pB3 = __shfl_sync(FULL, pk, 16 + 12 + g);

        // Gathers (bf16 rows = 64B): LDG.64, 4 rows per warp-LDG.
        const uint2 mA0 = ut2[(pA0 & 0x7FFFFFFF) * 8 + c];
        const uint2 mA1 = ut2[(pA1 & 0x7FFFFFFF) * 8 + c];
        const uint2 mA2 = ut2[(pA2 & 0x7FFFFFFF) * 8 + c];
        const uint2 mA3 = ut2[(pA3 & 0x7FFFFFFF) * 8 + c];
        const uint2 mB0 = ut2[(pB0 & 0x7FFFFFFF) * 8 + c];
        const uint2 mB1 = ut2[(pB1 & 0x7FFFFFFF) * 8 + c];
        const uint2 mB2 = ut2[(pB2 & 0x7FFFFFFF) * 8 + c];
        const uint2 mB3 = ut2[(pB3 & 0x7FFFFFFF) * 8 + c];

        // Compress mask sign bits; frees the pk registers early.
        const unsigned mbA = ((unsigned)pA0 >> 31)        | (((unsigned)pA1 >> 30) & 2u)
                           | (((unsigned)pA2 >> 29) & 4u) | (((unsigned)pA3 >> 28) & 8u);
        const unsigned mbB = ((unsigned)pB0 >> 31)        | (((unsigned)pB1 >> 30) & 2u)
                           | (((unsigned)pB2 >> 29) & 4u) | (((unsigned)pB3 >> 28) & 8u);

        // Score partial dots (f32, bf16 unpack at use) + replicated reduce.
        float sA0 = fmaf(blo(mA0.x), vA.x, fmaf(bhi(mA0.x), vA.y,
                    fmaf(blo(mA0.y), vA.z, bhi(mA0.y) * vA.w)));
        float sA1 = fmaf(blo(mA1.x), vA.x, fmaf(bhi(mA1.x), vA.y,
                    fmaf(blo(mA1.y), vA.z, bhi(mA1.y) * vA.w)));
        float sA2 = fmaf(blo(mA2.x), vA.x, fmaf(bhi(mA2.x), vA.y,
                    fmaf(blo(mA2.y), vA.z, bhi(mA2.y) * vA.w)));
        float sA3 = fmaf(blo(mA3.x), vA.x, fmaf(bhi(mA3.x), vA.y,
                    fmaf(blo(mA3.y), vA.z, bhi(mA3.y) * vA.w)));
        float sB0 = fmaf(blo(mB0.x), vB.x, fmaf(bhi(mB0.x), vB.y,
                    fmaf(blo(mB0.y), vB.z, bhi(mB0.y) * vB.w)));
        float sB1 = fmaf(blo(mB1.x), vB.x, fmaf(bhi(mB1.x), vB.y,
                    fmaf(blo(mB1.y), vB.z, bhi(mB1.y) * vB.w)));
        float sB2 = fmaf(blo(mB2.x), vB.x, fmaf(bhi(mB2.x), vB.y,
                    fmaf(blo(mB2.y), vB.z, bhi(mB2.y) * vB.w)));
        float sB3 = fmaf(blo(mB3.x), vB.x, fmaf(bhi(mB3.x), vB.y,
                    fmaf(blo(mB3.y), vB.z, bhi(mB3.y) * vB.w)));

        sA0 += __shfl_xor_sync(FULL, sA0, 4); sA1 += __shfl_xor_sync(FULL, sA1, 4);
        sA2 += __shfl_xor_sync(FULL, sA2, 4); sA3 += __shfl_xor_sync(FULL, sA3, 4);
        sB0 += __shfl_xor_sync(FULL, sB0, 4); sB1 += __shfl_xor_sync(FULL, sB1, 4);
        sB2 += __shfl_xor_sync(FULL, sB2, 4); sB3 += __shfl_xor_sync(FULL, sB3, 4);
        sA0 += __shfl_xor_sync(FULL, sA0, 2); sA1 += __shfl_xor_sync(FULL, sA1, 2);
        sA2 += __shfl_xor_sync(FULL, sA2, 2); sA3 += __shfl_xor_sync(FULL, sA3, 2);
        sB0 += __shfl_xor_sync(FULL, sB0, 2); sB1 += __shfl_xor_sync(FULL, sB1, 2);
        sB2 += __shfl_xor_sync(FULL, sB2, 2); sB3 += __shfl_xor_sync(FULL, sB3, 2);
        sA0 += __shfl_xor_sync(FULL, sA0, 1); sA1 += __shfl_xor_sync(FULL, sA1, 1);
        sA2 += __shfl_xor_sync(FULL, sA2, 1); sA3 += __shfl_xor_sync(FULL, sA3, 1);
        sB0 += __shfl_xor_sync(FULL, sB0, 1); sB1 += __shfl_xor_sync(FULL, sB1, 1);
        sB2 += __shfl_xor_sync(FULL, sB2, 1); sB3 += __shfl_xor_sync(FULL, sB3, 1);

        // Masked weights, locally on every lane.
        const float wA0 = (mbA & 1u) ? (sA0 + bb) : 0.f;
        const float wA1 = (mbA & 2u) ? (sA1 + bb) : 0.f;
        const float wA2 = (mbA & 4u) ? (sA2 + bb) : 0.f;
        const float wA3 = (mbA & 8u) ? (sA3 + bb) : 0.f;
        const float wB0 = (mbB & 1u) ? (sB0 + bb) : 0.f;
        const float wB1 = (mbB & 2u) ? (sB1 + bb) : 0.f;
        const float wB2 = (mbB & 4u) ? (sB2 + bb) : 0.f;
        const float wB3 = (mbB & 8u) ? (sB3 + bb) : 0.f;

        // fu partials (unpack again), then reduce over g (xor 8, 16).
        float fAx = wA0 * blo(mA0.x), fAy = wA0 * bhi(mA0.x);
        float fAz = wA0 * blo(mA0.y), fAw = wA0 * bhi(mA0.y);
        fAx = fmaf(wA1, blo(mA1.x), fAx); fAy = fmaf(wA1, bhi(mA1.x), fAy);
        fAz = fmaf(wA1, blo(mA1.y), fAz); fAw = fmaf(wA1, bhi(mA1.y), fAw);
        fAx = fmaf(wA2, blo(mA2.x), fAx); fAy = fmaf(wA2, bhi(mA2.x), fAy);
        fAz = fmaf(wA2, blo(mA2.y), fAz); fAw = fmaf(wA2, bhi(mA2.y), fAw);
        fAx = fmaf(wA3, blo(mA3.x), fAx); fAy = fmaf(wA3, bhi(mA3.x), fAy);
        fAz = fmaf(wA3, blo(mA3.y), fAz); fAw = fmaf(wA3, bhi(mA3.y), fAw);

        float fBx = wB0 * blo(mB0.x), fBy = wB0 * bhi(mB0.x);
        float fBz = wB0 * blo(mB0.y), fBw = wB0 * bhi(mB0.y);
        fBx = fmaf(wB1, blo(mB1.x), fBx); fBy = fmaf(wB1, bhi(mB1.x), fBy);
        fBz = fmaf(wB1, blo(mB1.y), fBz); fBw = fmaf(wB1, bhi(mB1.y), fBw);
        fBx = fmaf(wB2, blo(mB2.x), fBx); fBy = fmaf(wB2, bhi(mB2.x), fBy);
        fBz = fmaf(wB2, blo(mB2.y), fBz); fBw = fmaf(wB2, bhi(mB2.y), fBw);
        fBx = fmaf(wB3, blo(mB3.x), fBx); fBy = fmaf(wB3, bhi(mB3.x), fBy);
        fBz = fmaf(wB3, blo(mB3.y), fBz); fBw = fmaf(wB3, bhi(mB3.y), fBw);

        fAx += __shfl_xor_sync(FULL, fAx, 8);  fAy += __shfl_xor_sync(FULL, fAy, 8);
        fAz += __shfl_xor_sync(FULL, fAz, 8);  fAw += __shfl_xor_sync(FULL, fAw, 8);
        fBx += __shfl_xor_sync(FULL, fBx, 8);  fBy += __shfl_xor_sync(FULL, fBy, 8);
        fBz += __shfl_xor_sync(FULL, fBz, 8);  fBw += __shfl_xor_sync(FULL, fBw, 8);
        fAx += __shfl_xor_sync(FULL, fAx, 16); fAy += __shfl_xor_sync(FULL, fAy, 16);
        fAz += __shfl_xor_sync(FULL, fAz, 16); fAw += __shfl_xor_sync(FULL, fAw, 16);
        fBx += __shfl_xor_sync(FULL, fBx, 16); fBy += __shfl_xor_sync(FULL, fBy, 16);
        fBz += __shfl_xor_sync(FULL, fBz, 16); fBw += __shfl_xor_sync(FULL, fBw, 16);

        // MLP layer 1. ne = fu*it.
        const float nAx = fAx * itA.x, nAy = fAy * itA.y;
        const float nAz = fAz * itA.z, nAw = fAw * itA.w;
        const float nBx = fBx * itB.x, nBy = fBy * itB.y;
        const float nBz = fBz * itB.z, nBw = fBw * itB.w;

        // Reload W1 slices from smem (volatile: never hoisted into regs).
        float a00,a01,a02,a03, b00,b01,b02,b03, c00,c01,c02,c03;
        float a10,a11,a12,a13, b10,b11,b12,b13, c10,c11,c12,c13;
        asm volatile("ld.shared.v4.f32 {%0,%1,%2,%3},[%4];"
            : "=f"(a00),"=f"(a01),"=f"(a02),"=f"(a03) : "r"(w1_0));
        asm volatile("ld.shared.v4.f32 {%0,%1,%2,%3},[%4];"
            : "=f"(b00),"=f"(b01),"=f"(b02),"=f"(b03) : "r"(w1_0 + 128));
        asm volatile("ld.shared.v4.f32 {%0,%1,%2,%3},[%4];"
            : "=f"(c00),"=f"(c01),"=f"(c02),"=f"(c03) : "r"(w1_0 + 256));
        asm volatile("ld.shared.v4.f32 {%0,%1,%2,%3},[%4];"
            : "=f"(a10),"=f"(a11),"=f"(a12),"=f"(a13) : "r"(w1_1));
        asm volatile("ld.shared.v4.f32 {%0,%1,%2,%3},[%4];"
            : "=f"(b10),"=f"(b11),"=f"(b12),"=f"(b13) : "r"(w1_1 + 128));
        asm volatile("ld.shared.v4.f32 {%0,%1,%2,%3},[%4];"
            : "=f"(c10),"=f"(c11),"=f"(c12),"=f"(c13) : "r"(w1_1 + 256));

        float PA0, PA1, PB0, PB1;
        {
            float t;
            t = a00 * nAx; t = fmaf(b00, fAx, t); t = fmaf(c00, itA.x, t);
            t = fmaf(a01, nAy, t); t = fmaf(b01, fAy, t); t = fmaf(c01, itA.y, t);
            t = fmaf(a02, nAz, t); t = fmaf(b02, fAz, t); t = fmaf(c02, itA.z, t);
            t = fmaf(a03, nAw, t); t = fmaf(b03, fAw, t); t = fmaf(c03, itA.w, t);
            PA0 = t;
            t = a10 * nAx; t = fmaf(b10, fAx, t); t = fmaf(c10, itA.x, t);
            t = fmaf(a11, nAy, t); t = fmaf(b11, fAy, t); t = fmaf(c11, itA.y, t);
            t = fmaf(a12, nAz, t); t = fmaf(b12, fAz, t); t = fmaf(c12, itA.z, t);
            t = fmaf(a13, nAw, t); t = fmaf(b13, fAw, t); t = fmaf(c13, itA.w, t);
            PA1 = t;
            t = a00 * nBx; t = fmaf(b00, fBx, t); t = fmaf(c00, itB.x, t);
            t = fmaf(a01, nBy, t); t = fmaf(b01, fBy, t); t = fmaf(c01, itB.y, t);
            t = fmaf(a02, nBz, t); t = fmaf(b02, fBz, t); t = fmaf(c02, itB.z, t);
            t = fmaf(a03, nBw, t); t = fmaf(b03, fBw, t); t = fmaf(c03, itB.w, t);
            PB0 = t;
            t = a10 * nBx; t = fmaf(b10, fBx, t); t = fmaf(c10, itB.x, t);
            t = fmaf(a11, nBy, t); t = fmaf(b11, fBy, t); t = fmaf(c11, itB.y, t);
            t = fmaf(a12, nBz, t); t = fmaf(b12, fBz, t); t = fmaf(c12, itB.z, t);
            t = fmaf(a13, nBw, t); t = fmaf(b13, fBw, t); t = fmaf(c13, itB.w, t);
            PB1 = t;
        }

        // Select-free MLP reduce (xor 4, 2, 1): lane owns H_{j0} per pair.
        float hA = PA0 + __shfl_xor_sync(FULL, PA1, 4);
        float hB = PB0 + __shfl_xor_sync(FULL, PB1, 4);
        hA += __shfl_xor_sync(FULL, hA, 2);
        hB += __shfl_xor_sync(FULL, hB, 2);
        hA += __shfl_xor_sync(FULL, hA, 1);
        hB += __shfl_xor_sync(FULL, hB, 1);

        // Output layer, combined half-split tail reduce for both pairs.
        const float tA = w2c * fmaxf(hA + b1c, 0.f);
        const float tB = w2c * fmaxf(hB + b1c, 0.f);
        float x    = half ? tB : tA;
        float send = half ? tA : tB;
        x += __shfl_xor_sync(FULL, send, 16);
        x += __shfl_xor_sync(FULL, x, 8);
        x += __shfl_xor_sync(FULL, x, 4);
        x += __shfl_xor_sync(FULL, x, 2);
        x += __shfl_xor_sync(FULL, x, 1);
        // lanes 0-15 hold tvA, lanes 16-31 hold tvB.

        const float y  = 1.f / (1.f + __expf(-(x + b2v)));
        const float yB = __shfl_sync(FULL, y, 16);
        if (lane == 0) {
            if (bB != bA) {
                *(float2*)(out + base) = make_float2(y, yB);
            } else {
                out[base] = y;
            }
        }
    }
}

// ---------------------------------------------------------------------------
extern "C" void kernel_launch(void* const* d_in, const int* in_sizes, int n_in,
                              void* d_out, int out_size)
{
    const int*   item_inputs = (const int*)  d_in[0];
    const int*   member_ids  = (const int*)  d_in[1];
    const void*  member_mask =               d_in[2];
    const float* user_table  = (const float*)d_in[3];
    const float* item_table  = (const float*)d_in[4];
    const float* W_bil       = (const float*)d_in[5];
    const float* b_bil       = (const float*)d_in[6];
    const float* W1          = (const float*)d_in[7];
    const float* b1          = (const float*)d_in[8];
    const float* W2          = (const float*)d_in[9];
    const float* b2          = (const float*)d_in[10];
    float* out = (float*)d_out;

    const int B  = in_sizes[0];
    int NU = in_sizes[3] / 32;
    if (NU > 100000) NU = 100000;   // g_ut16 capacity
    int NI = in_sizes[4] / 32;
    if (NI > 50000) NI = 50000;     // g_vtab capacity

    const int n16 = NU * 4;         // uint4 stores (8 floats each)
    convert_kernel<<<(n16 + 255) / 256, 256>>>((const float4*)user_table, n16);
    vtab_kernel<<<(NI + 7) / 8, 256>>>(W_bil, item_table,
                                       (const unsigned int*)member_mask, NI);
    bilinear_main_kernel<<<1036, 128>>>(item_inputs, member_ids, member_mask,
                                        item_table, b_bil, W1, b1, W2, b2, out, B);
}

// round 13
// speedup vs baseline: 1.6095x; 1.2084x over previous
#include <cuda_runtime.h>

#define FULL 0xFFFFFFFFu

// Precomputed v[i,d] = sum_e W_bil[d,e] * item_table[i,e]  (NI=50000, D=32)
__device__ float g_vtab[50000 * 32];
// Mask dtype mode: 0 = int32, 1 = float32, 2 = uint8
__device__ int g_mask_mode;

// ---------------------------------------------------------------------------
// Precompute: one warp per item row: v = W_bil @ item_e. Sniffs mask dtype
// from word 0 (mask[0,0] guaranteed true since lengths >= 1).
// ---------------------------------------------------------------------------
__global__ void __launch_bounds__(256) vtab_kernel(
    const float* __restrict__ W_bil,
    const float* __restrict__ item_table,
    const unsigned int* __restrict__ mask_words,
    int NI)
{
    __shared__ float WT[32 * 33];
    int t = threadIdx.x;

    if (blockIdx.x == 0 && t == 0) {
        unsigned int w0 = mask_words[0];
        int mode;
        if (w0 == 1u)               mode = 0;
        else if (w0 == 0x3F800000u) mode = 1;
        else                        mode = 2;
        g_mask_mode = mode;
    }

    for (int k = t; k < 1024; k += blockDim.x) {
        int d = k >> 5, e = k & 31;
        WT[e * 33 + d] = W_bil[k];
    }
    __syncthreads();

    int warp = t >> 5, lane = t & 31;
    int i = blockIdx.x * (blockDim.x >> 5) + warp;
    if (i >= NI) return;

    float x = item_table[i * 32 + lane];
    float v = 0.f;
    #pragma unroll
    for (int e = 0; e < 32; e++)
        v = fmaf(WT[e * 33 + lane], __shfl_sync(FULL, x, e), v);
    g_vtab[i * 32 + lane] = v;
}

__device__ __forceinline__ float dot4(const float4 a, const float4 b) {
    return fmaf(a.x, b.x, fmaf(a.y, b.y, fmaf(a.z, b.z, a.w * b.w)));
}

// ---------------------------------------------------------------------------
// Main kernel: one warp, TWO pairs per iteration (ILP=2). lane = (g = lane>>3
// member-group, c = lane&7 float4 dim-chunk). Slot i = member 4i+g (4-line
// gathers). Scalar control words (member ids+mask word pk, item indices) are
// prefetched one iteration ahead so the shfl->gather chain issues at loop top.
// W1 lives in smem, reloaded per iteration (volatile).
// ---------------------------------------------------------------------------
__global__ void __launch_bounds__(256, 3) bilinear_main_kernel(
    const int*           __restrict__ item_inputs,
    const int*           __restrict__ member_ids,
    const void*          __restrict__ member_mask,
    const float*         __restrict__ user_table,
    const float*         __restrict__ item_table,
    const float*         __restrict__ b_bil,
    const float*         __restrict__ W1,
    const float*         __restrict__ b1,
    const float*         __restrict__ W2,
    const float*         __restrict__ b2,
    float*               __restrict__ out,
    int B)
{
    __shared__ float w1s[768];      // W1 [8][96]
    for (int k = threadIdx.x; k < 768; k += 256) w1s[k] = W1[k];
    __syncthreads();

    const int lane   = threadIdx.x & 31;
    const int warp   = (blockIdx.x * blockDim.x + threadIdx.x) >> 5;
    const int nwarps = (gridDim.x * blockDim.x) >> 5;

    const int g   = lane >> 3;        // member group 0..3
    const int c   = lane & 7;         // dim chunk 0..7 (dims 4c..4c+3)
    const int rho = (c >> 2) & 1;

    const int j0 = 2 * g + rho;       // owned MLP unit
    const int j1 = 2 * g + (1 ^ rho);

    const float b1c = b1[j0];
    const float w2c = W2[j0] * 0.25f;
    const float bb  = b_bil[0];
    const float b2v = b2[0];
    const int   mmode = g_mask_mode;
    const int   half  = lane >> 4;
    const int   memi  = lane & 15;

    const unsigned w1_0 = (unsigned)__cvta_generic_to_shared(&w1s[j0 * 96 + 4 * c]);
    const unsigned w1_1 = (unsigned)__cvta_generic_to_shared(&w1s[j1 * 96 + 4 * c]);

    const float4* __restrict__ ut4  = (const float4*)user_table;
    const float4* __restrict__ it4p = (const float4*)item_table;
    const float4* __restrict__ vt4p = (const float4*)g_vtab;

    // ---- prefetch scalar control for the first iteration ----
    const int step = 2 * nwarps;
    int base = 2 * warp;

    int pk, itmA, itmB;
    {
        const int bA0 = (base     < B) ? base     : (B - 1);
        const int bB0 = (base + 1 < B) ? base + 1 : (B - 1);
        itmA = item_inputs[bA0];
        itmB = item_inputs[bB0];
        const int bH = half ? bB0 : bA0;
        const int mid = member_ids[bH * 16 + memi];
        int mkbit;
        if (mmode == 0)      mkbit = (((const int*)member_mask)[bH * 16 + memi] != 0);
        else if (mmode == 1) mkbit = (((const float*)member_mask)[bH * 16 + memi] != 0.f);
        else                 mkbit = (((const unsigned char*)member_mask)[bH * 16 + memi] != 0);
        pk = mid | (mkbit << 31);
    }

    for (; base < B; base += step) {
        // ---- issue this iteration's gathers off the prefetched scalars ----
        const int pA0 = __shfl_sync(FULL, pk,      0 + g);
        const int pA1 = __shfl_sync(FULL, pk,      4 + g);
        const int pA2 = __shfl_sync(FULL, pk,      8 + g);
        const int pA3 = __shfl_sync(FULL, pk,     12 + g);
        const int pB0 = __shfl_sync(FULL, pk, 16 + 0 + g);
        const int pB1 = __shfl_sync(FULL, pk, 16 + 4 + g);
        const int pB2 = __shfl_sync(FULL, pk, 16 + 8 + g);
        const int pB3 = __shfl_sync(FULL, pk, 16 + 12 + g);

        const float4 mA0 = ut4[(pA0 & 0x7FFFFFFF) * 8 + c];
        const float4 mA1 = ut4[(pA1 & 0x7FFFFFFF) * 8 + c];
        const float4 mA2 = ut4[(pA2 & 0x7FFFFFFF) * 8 + c];
        const float4 mA3 = ut4[(pA3 & 0x7FFFFFFF) * 8 + c];
        const float4 mB0 = ut4[(pB0 & 0x7FFFFFFF) * 8 + c];
        const float4 mB1 = ut4[(pB1 & 0x7FFFFFFF) * 8 + c];
        const float4 mB2 = ut4[(pB2 & 0x7FFFFFFF) * 8 + c];
        const float4 mB3 = ut4[(pB3 & 0x7FFFFFFF) * 8 + c];

        const float4 itA = it4p[itmA * 8 + c];
        const float4 vA  = vt4p[itmA * 8 + c];
        const float4 itB = it4p[itmB * 8 + c];
        const float4 vB  = vt4p[itmB * 8 + c];

        // Compress mask sign bits; frees pk slots.
        const unsigned mbA = ((unsigned)pA0 >> 31)        | (((unsigned)pA1 >> 30) & 2u)
                           | (((unsigned)pA2 >> 29) & 4u) | (((unsigned)pA3 >> 28) & 8u);
        const unsigned mbB = ((unsigned)pB0 >> 31)        | (((unsigned)pB1 >> 30) & 2u)
                           | (((unsigned)pB2 >> 29) & 4u) | (((unsigned)pB3 >> 28) & 8u);

        // ---- prefetch next iteration's scalar control (overlaps compute) ----
        {
            const int nb  = base + step;
            const int bAn = (nb     < B) ? nb     : (B - 1);
            const int bBn = (nb + 1 < B) ? nb + 1 : (B - 1);
            itmA = item_inputs[bAn];
            itmB = item_inputs[bBn];
            const int bH = half ? bBn : bAn;
            const int mid = member_ids[bH * 16 + memi];
            int mkbit;
            if (mmode == 0)      mkbit = (((const int*)member_mask)[bH * 16 + memi] != 0);
            else if (mmode == 1) mkbit = (((const float*)member_mask)[bH * 16 + memi] != 0.f);
            else                 mkbit = (((const unsigned char*)member_mask)[bH * 16 + memi] != 0);
            pk = mid | (mkbit << 31);
        }

        // ---- score partial dots + replicated reduce over the c-group ----
        float sA0 = dot4(mA0, vA), sA1 = dot4(mA1, vA);
        float sA2 = dot4(mA2, vA), sA3 = dot4(mA3, vA);
        float sB0 = dot4(mB0, vB), sB1 = dot4(mB1, vB);
        float sB2 = dot4(mB2, vB), sB3 = dot4(mB3, vB);

        sA0 += __shfl_xor_sync(FULL, sA0, 4); sA1 += __shfl_xor_sync(FULL, sA1, 4);
        sA2 += __shfl_xor_sync(FULL, sA2, 4); sA3 += __shfl_xor_sync(FULL, sA3, 4);
        sB0 += __shfl_xor_sync(FULL, sB0, 4); sB1 += __shfl_xor_sync(FULL, sB1, 4);
        sB2 += __shfl_xor_sync(FULL, sB2, 4); sB3 += __shfl_xor_sync(FULL, sB3, 4);
        sA0 += __shfl_xor_sync(FULL, sA0, 2); sA1 += __shfl_xor_sync(FULL, sA1, 2);
        sA2 += __shfl_xor_sync(FULL, sA2, 2); sA3 += __shfl_xor_sync(FULL, sA3, 2);
        sB0 += __shfl_xor_sync(FULL, sB0, 2); sB1 += __shfl_xor_sync(FULL, sB1, 2);
        sB2 += __shfl_xor_sync(FULL, sB2, 2); sB3 += __shfl_xor_sync(FULL, sB3, 2);
        sA0 += __shfl_xor_sync(FULL, sA0, 1); sA1 += __shfl_xor_sync(FULL, sA1, 1);
        sA2 += __shfl_xor_sync(FULL, sA2, 1); sA3 += __shfl_xor_sync(FULL, sA3, 1);
        sB0 += __shfl_xor_sync(FULL, sB0, 1); sB1 += __shfl_xor_sync(FULL, sB1, 1);
        sB2 += __shfl_xor_sync(FULL, sB2, 1); sB3 += __shfl_xor_sync(FULL, sB3, 1);

        // Masked weights, locally on every lane.
        const float wA0 = (mbA & 1u) ? (sA0 + bb) : 0.f;
        const float wA1 = (mbA & 2u) ? (sA1 + bb) : 0.f;
        const float wA2 = (mbA & 4u) ? (sA2 + bb) : 0.f;
        const float wA3 = (mbA & 8u) ? (sA3 + bb) : 0.f;
        const float wB0 = (mbB & 1u) ? (sB0 + bb) : 0.f;
        const float wB1 = (mbB & 2u) ? (sB1 + bb) : 0.f;
        const float wB2 = (mbB & 4u) ? (sB2 + bb) : 0.f;
        const float wB3 = (mbB & 8u) ? (sB3 + bb) : 0.f;

        // fu partials, then reduce over g (xor 8, 16).
        float fAx = wA0 * mA0.x, fAy = wA0 * mA0.y, fAz = wA0 * mA0.z, fAw = wA0 * mA0.w;
        fAx = fmaf(wA1, mA1.x, fAx); fAy = fmaf(wA1, mA1.y, fAy);
        fAz = fmaf(wA1, mA1.z, fAz); fAw = fmaf(wA1, mA1.w, fAw);
        fAx = fmaf(wA2, mA2.x, fAx); fAy = fmaf(wA2, mA2.y, fAy);
        fAz = fmaf(wA2, mA2.z, fAz); fAw = fmaf(wA2, mA2.w, fAw);
        fAx = fmaf(wA3, mA3.x, fAx); fAy = fmaf(wA3, mA3.y, fAy);
        fAz = fmaf(wA3, mA3.z, fAz); fAw = fmaf(wA3, mA3.w, fAw);

        float fBx = wB0 * mB0.x, fBy = wB0 * mB0.y, fBz = wB0 * mB0.z, fBw = wB0 * mB0.w;
        fBx = fmaf(wB1, mB1.x, fBx); fBy = fmaf(wB1, mB1.y, fBy);
        fBz = fmaf(wB1, mB1.z, fBz); fBw = fmaf(wB1, mB1.w, fBw);
        fBx = fmaf(wB2, mB2.x, fBx); fBy = fmaf(wB2, mB2.y, fBy);
        fBz = fmaf(wB2, mB2.z, fBz); fBw = fmaf(wB2, mB2.w, fBw);
        fBx = fmaf(wB3, mB3.x, fBx); fBy = fmaf(wB3, mB3.y, fBy);
        fBz = fmaf(wB3, mB3.z, fBz); fBw = fmaf(wB3, mB3.w, fBw);

        fAx += __shfl_xor_sync(FULL, fAx, 8);  fAy += __shfl_xor_sync(FULL, fAy, 8);
        fAz += __shfl_xor_sync(FULL, fAz, 8);  fAw += __shfl_xor_sync(FULL, fAw, 8);
        fBx += __shfl_xor_sync(FULL, fBx, 8);  fBy += __shfl_xor_sync(FULL, fBy, 8);
        fBz += __shfl_xor_sync(FULL, fBz, 8);  fBw += __shfl_xor_sync(FULL, fBw, 8);
        fAx += __shfl_xor_sync(FULL, fAx, 16); fAy += __shfl_xor_sync(FULL, fAy, 16);
        fAz += __shfl_xor_sync(FULL, fAz, 16); fAw += __shfl_xor_sync(FULL, fAw, 16);
        fBx += __shfl_xor_sync(FULL, fBx, 16); fBy += __shfl_xor_sync(FULL, fBy, 16);
        fBz += __shfl_xor_sync(FULL, fBz, 16); fBw += __shfl_xor_sync(FULL, fBw, 16);

        // MLP layer 1. ne = fu*it.
        const float nAx = fAx * itA.x, nAy = fAy * itA.y;
        const float nAz = fAz * itA.z, nAw = fAw * itA.w;
        const float nBx = fBx * itB.x, nBy = fBy * itB.y;
        const float nBz = fBz * itB.z, nBw = fBw * itB.w;

        // Reload W1 slices from smem (volatile: never hoisted into regs).
        float a00,a01,a02,a03, b00,b01,b02,b03, c00,c01,c02,c03;
        float a10,a11,a12,a13, b10,b11,b12,b13, c10,c11,c12,c13;
        asm volatile("ld.shared.v4.f32 {%0,%1,%2,%3},[%4];"
            : "=f"(a00),"=f"(a01),"=f"(a02),"=f"(a03) : "r"(w1_0));
        asm volatile("ld.shared.v4.f32 {%0,%1,%2,%3},[%4];"
            : "=f"(b00),"=f"(b01),"=f"(b02),"=f"(b03) : "r"(w1_0 + 128));
        asm volatile("ld.shared.v4.f32 {%0,%1,%2,%3},[%4];"
            : "=f"(c00),"=f"(c01),"=f"(c02),"=f"(c03) : "r"(w1_0 + 256));
        asm volatile("ld.shared.v4.f32 {%0,%1,%2,%3},[%4];"
            : "=f"(a10),"=f"(a11),"=f"(a12),"=f"(a13) : "r"(w1_1));
        asm volatile("ld.shared.v4.f32 {%0,%1,%2,%3},[%4];"
            : "=f"(b10),"=f"(b11),"=f"(b12),"=f"(b13) : "r"(w1_1 + 128));
        asm volatile("ld.shared.v4.f32 {%0,%1,%2,%3},[%4];"
            : "=f"(c10),"=f"(c11),"=f"(c12),"=f"(c13) : "r"(w1_1 + 256));

        float PA0, PA1, PB0, PB1;
        {
            float t;
            t = a00 * nAx; t = fmaf(b00, fAx, t); t = fmaf(c00, itA.x, t);
            t = fmaf(a01, nAy, t); t = fmaf(b01, fAy, t); t = fmaf(c01, itA.y, t);
            t = fmaf(a02, nAz, t); t = fmaf(b02, fAz, t); t = fmaf(c02, itA.z, t);
            t = fmaf(a03, nAw, t); t = fmaf(b03, fAw, t); t = fmaf(c03, itA.w, t);
            PA0 = t;
            t = a10 * nAx; t = fmaf(b10, fAx, t); t = fmaf(c10, itA.x, t);
            t = fmaf(a11, nAy, t); t = fmaf(b11, fAy, t); t = fmaf(c11, itA.y, t);
            t = fmaf(a12, nAz, t); t = fmaf(b12, fAz, t); t = fmaf(c12, itA.z, t);
            t = fmaf(a13, nAw, t); t = fmaf(b13, fAw, t); t = fmaf(c13, itA.w, t);
            PA1 = t;
            t = a00 * nBx; t = fmaf(b00, fBx, t); t = fmaf(c00, itB.x, t);
            t = fmaf(a01, nBy, t); t = fmaf(b01, fBy, t); t = fmaf(c01, itB.y, t);
            t = fmaf(a02, nBz, t); t = fmaf(b02, fBz, t); t = fmaf(c02, itB.z, t);
            t = fmaf(a03, nBw, t); t = fmaf(b03, fBw, t); t = fmaf(c03, itB.w, t);
            PB0 = t;
            t = a10 * nBx; t = fmaf(b10, fBx, t); t = fmaf(c10, itB.x, t);
            t = fmaf(a11, nBy, t); t = fmaf(b11, fBy, t); t = fmaf(c11, itB.y, t);
            t = fmaf(a12, nBz, t); t = fmaf(b12, fBz, t); t = fmaf(c12, itB.z, t);
            t = fmaf(a13, nBw, t); t = fmaf(b13, fBw, t); t = fmaf(c13, itB.w, t);
            PB1 = t;
        }

        // Select-free MLP reduce (xor 4, 2, 1): lane owns H_{j0} per pair.
        float hA = PA0 + __shfl_xor_sync(FULL, PA1, 4);
        float hB = PB0 + __shfl_xor_sync(FULL, PB1, 4);
        hA += __shfl_xor_sync(FULL, hA, 2);
        hB += __shfl_xor_sync(FULL, hB, 2);
        hA += __shfl_xor_sync(FULL, hA, 1);
        hB += __shfl_xor_sync(FULL, hB, 1);

        // Output layer, combined half-split tail reduce for both pairs.
        const float tA = w2c * fmaxf(hA + b1c, 0.f);
        const float tB = w2c * fmaxf(hB + b1c, 0.f);
        float x    = half ? tB : tA;
        float send = half ? tA : tB;
        x += __shfl_xor_sync(FULL, send, 16);
        x += __shfl_xor_sync(FULL, x, 8);
        x += __shfl_xor_sync(FULL, x, 4);
        x += __shfl_xor_sync(FULL, x, 2);
        x += __shfl_xor_sync(FULL, x, 1);
        // lanes 0-15 hold tvA, lanes 16-31 hold tvB.

        const float y  = 1.f / (1.f + __expf(-(x + b2v)));
        const float yB = __shfl_sync(FULL, y, 16);
        if (lane == 0) {
            if (base + 1 < B) {
                *(float2*)(out + base) = make_float2(y, yB);
            } else {
                out[base] = y;
            }
        }
    }
}

// ---------------------------------------------------------------------------
extern "C" void kernel_launch(void* const* d_in, const int* in_sizes, int n_in,
                              void* d_out, int out_size)
{
    const int*   item_inputs = (const int*)  d_in[0];
    const int*   member_ids  = (const int*)  d_in[1];
    const void*  member_mask =               d_in[2];
    const float* user_table  = (const float*)d_in[3];
    const float* item_table  = (const float*)d_in[4];
    const float* W_bil       = (const float*)d_in[5];
    const float* b_bil       = (const float*)d_in[6];
    const float* W1          = (const float*)d_in[7];
    const float* b1          = (const float*)d_in[8];
    const float* W2          = (const float*)d_in[9];
    const float* b2          = (const float*)d_in[10];
    float* out = (float*)d_out;

    const int B  = in_sizes[0];
    int NI = in_sizes[4] / 32;
    if (NI > 50000) NI = 50000;   // g_vtab capacity (problem spec: NI = 50000)

    vtab_kernel<<<(NI + 7) / 8, 256>>>(W_bil, item_table,
                                       (const unsigned int*)member_mask, NI);
    bilinear_main_kernel<<<444, 256>>>(item_inputs, member_ids, member_mask,
                                       user_table, item_table,
                                       b_bil, W1, b1, W2, b2, out, B);
}